// round 3
// baseline (speedup 1.0000x reference)
#include <cuda_runtime.h>

// LSTMMultistep: B=256, T=2048, L=4, H=64, P=1 (input & proj size 1).
// Persistent kernel: one block per batch element, 4 warps = 4 layers,
// software-pipelined over time (warp l processes t = s - l at global step s).
// Scalar h handoff between layers through a tiny smem ring + __syncthreads.

#define TT 2048
#define BB 256
#define LL 4
#define HH 64
#define NG 256   // 4*H

__device__ __forceinline__ float ex2f(float x) {
    float r; asm("ex2.approx.f32 %0, %1;" : "=f"(r) : "f"(x)); return r;
}
__device__ __forceinline__ float rcpf(float x) {
    float r; asm("rcp.approx.f32 %0, %1;" : "=f"(r) : "f"(x)); return r;
}

__global__ __launch_bounds__(128, 2)
void lstm_pipe_kernel(const float* __restrict__ y,
                      const float* __restrict__ Wih,
                      const float* __restrict__ Whh,
                      const float* __restrict__ bih,
                      const float* __restrict__ bhh,
                      const float* __restrict__ Whr,
                      float* __restrict__ out,
                      int msl)
{
    __shared__ float xbuf[TT];        // full input sequence for this batch elem
    __shared__ float hring[LL][2];    // layer-l output h at time parity t&1

    const int b    = blockIdx.x;
    const int tid  = threadIdx.x;
    const int l    = tid >> 5;        // warp id = layer id
    const int lane = tid & 31;

    // Stage the whole input sequence (P=1 -> y[b, t, 0] = y[b*T + t])
    const float* yb = y + (size_t)b * TT;
    for (int i = tid; i < TT; i += 128) xbuf[i] = yb[i];

    // ---- Load per-lane weights: units u0 = lane, u1 = lane + 32 ----
    // Gate order (torch): i, f, g, o in blocks of H=64.
    // Pre-scale so each nonlinearity is one EX2:
    //   sigmoid(x) = 1 / (1 + 2^(x * -log2(e)))
    //   tanh(x)    = (1 - e) / (1 + e),  e = 2^(x * -2*log2(e))
    const float NL2E  = -1.4426950408889634f;   // -log2(e)   (gates i, f, o)
    const float N2L2E = -2.8853900817779268f;   // -2*log2(e) (gate g, tanh(c))

    const float* wih = Wih + l * NG;   // [4H] (P=1)
    const float* whh = Whh + l * NG;
    const float* bi  = bih + l * NG;
    const float* bh  = bhh + l * NG;
    const float* wr  = Whr + l * HH;   // [1, H]

    float awi[2][4], awh[2][4], ab[2][4], awr[2];
#pragma unroll
    for (int u = 0; u < 2; u++) {
        int uu = lane + u * 32;
#pragma unroll
        for (int g = 0; g < 4; g++) {
            float s = (g == 2) ? N2L2E : NL2E;
            awi[u][g] = s * wih[g * HH + uu];
            awh[u][g] = s * whh[g * HH + uu];
            ab[u][g]  = s * (bi[g * HH + uu] + bh[g * HH + uu]);
        }
        awr[u] = wr[uu];
    }

    float c0 = 0.0f, c1 = 0.0f, h = 0.0f;
    __syncthreads();

    const int S = TT + LL - 1;  // 2051 pipelined steps
    const int Tout = TT - msl;

    for (int s = 0; s < S; s++) {
        const int t = s - l;
        if (t >= 0 && t < TT) {
            // layer input: original y for layer 0, previous layer's h otherwise
            float x = (l == 0) ? xbuf[t] : hring[l - 1][t & 1];

            // gate linear terms (pre-scaled): a = s*(W_ih x + b + W_hh h)
            float a[2][4];
#pragma unroll
            for (int u = 0; u < 2; u++)
#pragma unroll
                for (int g = 0; g < 4; g++)
                    a[u][g] = fmaf(h, awh[u][g], fmaf(x, awi[u][g], ab[u][g]));

            float contrib0, contrib1;
#pragma unroll
            for (int u = 0; u < 2; u++) {
                float ei = ex2f(a[u][0]);   // exp(-i)
                float ef = ex2f(a[u][1]);   // exp(-f)
                float eg = ex2f(a[u][2]);   // exp(-2g)
                float eo = ex2f(a[u][3]);   // exp(-o)

                float sf  = rcpf(1.0f + ef);                    // sigmoid(f)
                float rig = rcpf((1.0f + ei) * (1.0f + eg));    // shared RCP
                float t1  = (1.0f - eg) * rig;                  // sig(i)*tanh(g)

                float c = (u == 0) ? c0 : c1;
                c = fmaf(sf, c, t1);
                if (u == 0) c0 = c; else c1 = c;

                float ec  = ex2f(c * N2L2E);                    // exp(-2c)
                float roc = rcpf((1.0f + eo) * (1.0f + ec));    // shared RCP
                float cb  = (1.0f - ec) * awr[u] * roc;         // sig(o)*tanh(c)*whr
                if (u == 0) contrib0 = cb; else contrib1 = cb;
            }

            // h = sum over 64 units (projection, P=1): butterfly reduce
            float p = contrib0 + contrib1;
#pragma unroll
            for (int off = 16; off; off >>= 1)
                p += __shfl_xor_sync(0xffffffffu, p, off);
            h = p;

            if (lane == 0) {
                hring[l][t & 1] = h;
                if (l == LL - 1 && t >= msl)
                    out[(size_t)b * Tout + (t - msl)] = h;
            }
        }
        __syncthreads();
    }
}

extern "C" void kernel_launch(void* const* d_in, const int* in_sizes, int n_in,
                              void* d_out, int out_size)
{
    const float* y   = (const float*)d_in[0];
    const float* Wih = (const float*)d_in[1];
    const float* Whh = (const float*)d_in[2];
    const float* bih = (const float*)d_in[3];
    const float* bhh = (const float*)d_in[4];
    const float* Whr = (const float*)d_in[5];
    // infer min_seq_len from output size (avoids d_in[6] dtype ambiguity):
    // out_size = B * (T - msl) * P
    int msl = TT - out_size / BB;

    lstm_pipe_kernel<<<BB, 128>>>(y, Wih, Whh, bih, bhh, Whr,
                                  (float*)d_out, msl);
}

// round 5
// speedup vs baseline: 1.0096x; 1.0096x over previous
#include <cuda_runtime.h>

// LSTMMultistep: B=256, T=2048, L=4, H=64, P=1.
// One block per batch element, warp l = layer l. Warps FREE-RUN (no per-step
// __syncthreads): each layer streams its scalar h(t) into a full-length smem
// buffer and publishes progress with st.release; consumers poll with
// ld.acquire only when they catch up. Cross-unit RCP merging cuts MUFU ops
// from 16 to 12 per warp-step.

#define TT 2048
#define BB 256
#define LL 4
#define HH 64
#define NG 256   // 4*H

__device__ __forceinline__ float ex2f(float x) {
    float r; asm("ex2.approx.f32 %0, %1;" : "=f"(r) : "f"(x)); return r;
}
__device__ __forceinline__ float rcpf(float x) {
    float r; asm("rcp.approx.f32 %0, %1;" : "=f"(r) : "f"(x)); return r;
}
__device__ __forceinline__ unsigned smem_addr(const void* p) {
    return (unsigned)__cvta_generic_to_shared(p);
}
__device__ __forceinline__ void st_release_shared(unsigned addr, unsigned v) {
    asm volatile("st.release.cta.shared.u32 [%0], %1;" :: "r"(addr), "r"(v) : "memory");
}
__device__ __forceinline__ unsigned ld_acquire_shared(unsigned addr) {
    unsigned v;
    asm volatile("ld.acquire.cta.shared.u32 %0, [%1];" : "=r"(v) : "r"(addr) : "memory");
    return v;
}

__global__ __launch_bounds__(128, 2)
void lstm_pipe_kernel(const float* __restrict__ y,
                      const float* __restrict__ Wih,
                      const float* __restrict__ Whh,
                      const float* __restrict__ bih,
                      const float* __restrict__ bhh,
                      const float* __restrict__ Whr,
                      float* __restrict__ out,
                      int msl)
{
    __shared__ float xbuf[TT];            // layer-0 input stream (8 KB)
    __shared__ float hbuf[LL - 1][TT];    // full h streams for layers 0..2 (24 KB)
    __shared__ unsigned prog[LL];         // steps completed per layer

    const int b    = blockIdx.x;
    const int tid  = threadIdx.x;
    const int l    = tid >> 5;            // warp id = layer id
    const int lane = tid & 31;

    // stage input sequence (P=1)
    const float* yb = y + (size_t)b * TT;
    for (int i = tid; i < TT; i += 128) xbuf[i] = yb[i];
    if (tid < LL) prog[tid] = 0u;

    // pre-scaled weights: sigmoid(x)=1/(1+2^(-x*log2e)), tanh(x)=(1-e)/(1+e), e=2^(-2x*log2e)
    const float NL2E  = -1.4426950408889634f;
    const float N2L2E = -2.8853900817779268f;

    const float* wih = Wih + l * NG;
    const float* whh = Whh + l * NG;
    const float* bi  = bih + l * NG;
    const float* bh  = bhh + l * NG;
    const float* wr  = Whr + l * HH;

    float awi[2][4], awh[2][4], ab[2][4], awr[2];
#pragma unroll
    for (int u = 0; u < 2; u++) {
        int uu = lane + u * 32;
#pragma unroll
        for (int g = 0; g < 4; g++) {
            float s = (g == 2) ? N2L2E : NL2E;
            awi[u][g] = s * wih[g * HH + uu];
            awh[u][g] = s * whh[g * HH + uu];
            ab[u][g]  = s * (bi[g * HH + uu] + bh[g * HH + uu]);
        }
        awr[u] = wr[uu];
    }

    __syncthreads();   // the ONLY block-wide barrier

    const unsigned my_prog   = smem_addr(&prog[l]);
    const unsigned prev_prog = (l > 0) ? smem_addr(&prog[l - 1]) : 0u;
    const float* xs = (l == 0) ? xbuf : hbuf[l - 1];

    float c0 = 0.0f, c1 = 0.0f, h = 0.0f;
    int avail = (l == 0) ? TT : 0;
    const int Tout = TT - msl;

    // fetch x for t=0 (blocking if needed)
    if (0 >= avail) {
        unsigned av;
        do { av = ld_acquire_shared(prev_prog); } while ((int)av <= 0);
        avail = (int)av;
    }
    float x = xs[0];
    bool have_x = true;

    for (int t = 0; t < TT; t++) {
        if (!have_x) {          // prefetch missed last step: blocking poll
            if (t >= avail) {
                unsigned av;
                do { av = ld_acquire_shared(prev_prog); } while ((int)av <= t);
                avail = (int)av;
            }
            x = xs[t];
        }

        // gate pre-activations (pre-scaled): a = h*awh + (x*awi + ab)
        float a[2][4];
#pragma unroll
        for (int u = 0; u < 2; u++)
#pragma unroll
            for (int g = 0; g < 4; g++)
                a[u][g] = fmaf(h, awh[u][g], fmaf(x, awi[u][g], ab[u][g]));

        float ei0 = ex2f(a[0][0]), ef0 = ex2f(a[0][1]), eg0 = ex2f(a[0][2]), eo0 = ex2f(a[0][3]);
        float ei1 = ex2f(a[1][0]), ef1 = ex2f(a[1][1]), eg1 = ex2f(a[1][2]), eo1 = ex2f(a[1][3]);

        // ---- non-blocking prefetch of x(t+1): off the critical chain ----
        have_x = false;
        int tn = t + 1;
        if (tn < TT) {
            if (tn < avail) { x = xs[tn]; have_x = true; }
            else if (l > 0) {
                unsigned av = ld_acquire_shared(prev_prog);
                if ((int)av > tn) { avail = (int)av; x = xs[tn]; have_x = true; }
            }
        } else have_x = true;

        // ---- cell update, one RCP for both units ----
        // c' = [c*(1+ei)(1+eg) + (1-eg)(1+ef)] / [(1+ef)(1+ei)(1+eg)]
        float B0 = (1.0f + ei0) * (1.0f + eg0), A0 = 1.0f + ef0;
        float B1 = (1.0f + ei1) * (1.0f + eg1), A1 = 1.0f + ef1;
        float D0 = A0 * B0, D1 = A1 * B1;
        float R1 = rcpf(D0 * D1);
        float N0 = fmaf(c0, B0, (1.0f - eg0) * A0);
        float N1 = fmaf(c1, B1, (1.0f - eg1) * A1);
        c0 = N0 * (R1 * D1);
        c1 = N1 * (R1 * D0);

        // ---- output gate * tanh(c) * W_hr, one RCP for both units ----
        float ec0 = ex2f(c0 * N2L2E);
        float ec1 = ex2f(c1 * N2L2E);
        float E0 = (1.0f + eo0) * (1.0f + ec0);
        float E1 = (1.0f + eo1) * (1.0f + ec1);
        float R2 = rcpf(E0 * E1);
        float p = (1.0f - ec0) * awr[0] * (R2 * E1)
                + (1.0f - ec1) * awr[1] * (R2 * E0);

        // 64-unit projection reduction (P=1): warp butterfly
#pragma unroll
        for (int off = 16; off; off >>= 1)
            p += __shfl_xor_sync(0xffffffffu, p, off);
        h = p;

        if (l < LL - 1) {
            if (lane == 0) {
                hbuf[l][t] = h;
                st_release_shared(my_prog, (unsigned)(t + 1));
            }
        } else if (lane == 0 && t >= msl) {
            out[(size_t)b * Tout + (t - msl)] = h;
        }
    }
}

extern "C" void kernel_launch(void* const* d_in, const int* in_sizes, int n_in,
                              void* d_out, int out_size)
{
    const float* y   = (const float*)d_in[0];
    const float* Wih = (const float*)d_in[1];
    const float* Whh = (const float*)d_in[2];
    const float* bih = (const float*)d_in[3];
    const float* bhh = (const float*)d_in[4];
    const float* Whr = (const float*)d_in[5];
    int msl = TT - out_size / BB;   // out_size = B * (T - msl)

    lstm_pipe_kernel<<<BB, 128>>>(y, Wih, Whh, bih, bhh, Whr,
                                  (float*)d_out, msl);
}

// round 8
// speedup vs baseline: 1.4404x; 1.4267x over previous
#include <cuda_runtime.h>

// LSTMMultistep: B=256, T=2048, L=4, H=64, P=1.
// One block per batch element, warp l = layer l, free-running pipeline.
// - Handoff: hbuf word itself is the readiness flag (NaN sentinel): no fences,
//   no lane==0 branches, all-lane write-collapsed stores.
// - Reduction: raw-asm shfl.sync.bfly butterfly (no WARPSYNC envelope).
// - Nonlinearities: MUFU tanh.approx; sigmoid(x)=0.5*tanh(x/2)+0.5 with the
//   0.5 pre-folded into the i/f/o weight copies.

#define TT 2048
#define BB 256
#define LL 4
#define HH 64
#define NG 256   // 4*H

#define SENT 0xffc00000u   // -NaN bit pattern; real h is always finite

__device__ __forceinline__ float tanhfa(float x) {
    float r; asm("tanh.approx.f32 %0, %1;" : "=f"(r) : "f"(x)); return r;
}
__device__ __forceinline__ float shfl_bfly(float v, int mask) {
    float r;
    asm volatile("shfl.sync.bfly.b32 %0, %1, %2, 0x1f, 0xffffffff;"
                 : "=f"(r) : "f"(v), "r"(mask));
    return r;
}
__device__ __forceinline__ unsigned smem_u32(const void* p) {
    return (unsigned)__cvta_generic_to_shared(p);
}
__device__ __forceinline__ unsigned lds_volatile(unsigned addr) {
    unsigned v;
    asm volatile("ld.volatile.shared.b32 %0, [%1];" : "=r"(v) : "r"(addr) : "memory");
    return v;
}
__device__ __forceinline__ void sts_volatile(unsigned addr, unsigned v) {
    asm volatile("st.volatile.shared.b32 [%0], %1;" :: "r"(addr), "r"(v) : "memory");
}

__global__ __launch_bounds__(128, 2)
void lstm_pipe_kernel(const float* __restrict__ y,
                      const float* __restrict__ Wih,
                      const float* __restrict__ Whh,
                      const float* __restrict__ bih,
                      const float* __restrict__ bhh,
                      const float* __restrict__ Whr,
                      float* __restrict__ out,
                      int msl)
{
    __shared__ float xbuf[TT];            // layer-0 input stream (8 KB)
    __shared__ float hbuf[LL - 1][TT];    // h streams for layers 0..2 (24 KB)

    const int b    = blockIdx.x;
    const int tid  = threadIdx.x;
    const int l    = tid >> 5;            // warp id = layer id
    const int lane = tid & 31;

    // stage input sequence; poison hbuf with sentinel
    const float* yb = y + (size_t)b * TT;
    for (int i = tid; i < TT; i += 128) xbuf[i] = yb[i];
    {
        unsigned* hb = (unsigned*)&hbuf[0][0];
        for (int i = tid; i < (LL - 1) * TT; i += 128) hb[i] = SENT;
    }

    // Weight prep. sigmoid(x) = 0.5*tanh(0.5x) + 0.5  -> scale i/f/o rows 0.5.
    // tanh(g) direct -> g row unscaled.
    const float* wih = Wih + l * NG;
    const float* whh = Whh + l * NG;
    const float* bi  = bih + l * NG;
    const float* bh  = bhh + l * NG;
    const float* wr  = Whr + l * HH;

    float awi[2][4], awh[2][4], ab[2][4], awr2[2];
#pragma unroll
    for (int u = 0; u < 2; u++) {
        int uu = lane + u * 32;
#pragma unroll
        for (int g = 0; g < 4; g++) {
            float s = (g == 2) ? 1.0f : 0.5f;
            awi[u][g] = s * wih[g * HH + uu];
            awh[u][g] = s * whh[g * HH + uu];
            ab[u][g]  = s * (bi[g * HH + uu] + bh[g * HH + uu]);
        }
        awr2[u] = 0.5f * wr[uu];   // folds sigma(o)=0.5*to+0.5 multiply
    }

    __syncthreads();   // sentinel init + xbuf visible; only block-wide barrier

    const unsigned xs_base = smem_u32((l == 0) ? &xbuf[0] : &hbuf[l - 1][0]);
    const unsigned hb_base = (l < LL - 1) ? smem_u32(&hbuf[l][0]) : 0u;
    const bool is_mid = (l < LL - 1);
    const int  Tout   = TT - msl;
    float* outb = out + (size_t)b * Tout;

    float c0 = 0.0f, c1 = 0.0f, h = 0.0f;

    for (int t = 0; t < TT; t++) {
        // ---- fetch x(t): spin on the data word (sentinel = not ready) ----
        unsigned xb = lds_volatile(xs_base + 4u * t);
        while (xb == SENT) xb = lds_volatile(xs_base + 4u * t);
        const float x = __uint_as_float(xb);

        // pre-activations: a = h*awh + (x*awi + ab)   (pre-scaled)
        float a[2][4];
#pragma unroll
        for (int u = 0; u < 2; u++)
#pragma unroll
            for (int g = 0; g < 4; g++)
                a[u][g] = fmaf(h, awh[u][g], fmaf(x, awi[u][g], ab[u][g]));

        float p;
        {
            // unit 0
            float ti0 = tanhfa(a[0][0]);
            float tf0 = tanhfa(a[0][1]);
            float tg0 = tanhfa(a[0][2]);
            float to0 = tanhfa(a[0][3]);
            // unit 1
            float ti1 = tanhfa(a[1][0]);
            float tf1 = tanhfa(a[1][1]);
            float tg1 = tanhfa(a[1][2]);
            float to1 = tanhfa(a[1][3]);

            float sitg0 = tg0 * fmaf(ti0, 0.5f, 0.5f);   // sig(i)*tanh(g)
            float sitg1 = tg1 * fmaf(ti1, 0.5f, 0.5f);
            float sf0   = fmaf(tf0, 0.5f, 0.5f);         // sig(f)
            float sf1   = fmaf(tf1, 0.5f, 0.5f);
            c0 = fmaf(sf0, c0, sitg0);
            c1 = fmaf(sf1, c1, sitg1);

            float tc0 = tanhfa(c0);
            float tc1 = tanhfa(c1);
            // p_u = tanh(c) * sig(o) * wr = tc * (to*awr2 + awr2)
            p = tc0 * fmaf(to0, awr2[0], awr2[0])
              + tc1 * fmaf(to1, awr2[1], awr2[1]);
        }

        // 64-unit projection sum (P=1): raw butterfly, no sync envelope
        p += shfl_bfly(p, 16);
        p += shfl_bfly(p, 8);
        p += shfl_bfly(p, 4);
        p += shfl_bfly(p, 2);
        p += shfl_bfly(p, 1);
        h = p;

        // publish: all lanes write the same word (write-collapses); the word
        // itself flips sentinel -> valid. No fence, no lane predicate.
        if (is_mid) {
            sts_volatile(hb_base + 4u * t, __float_as_uint(h));
        } else if (t >= msl) {
            outb[t - msl] = h;   // all lanes same addr+value -> 1 transaction
        }
    }
}

extern "C" void kernel_launch(void* const* d_in, const int* in_sizes, int n_in,
                              void* d_out, int out_size)
{
    const float* y   = (const float*)d_in[0];
    const float* Wih = (const float*)d_in[1];
    const float* Whh = (const float*)d_in[2];
    const float* bih = (const float*)d_in[3];
    const float* bhh = (const float*)d_in[4];
    const float* Whr = (const float*)d_in[5];
    int msl = TT - out_size / BB;   // out_size = B * (T - msl)

    lstm_pipe_kernel<<<BB, 128>>>(y, Wih, Whh, bih, bhh, Whr,
                                  (float*)d_out, msl);
}